// round 3
// baseline (speedup 1.0000x reference)
#include <cuda_runtime.h>
#include <cstdint>

#define DINLINE __device__ __forceinline__

// ============================ helpers ============================
DINLINE uint32_t smem_u32(const void* p) {
    uint32_t a;
    asm("{ .reg .u64 t; cvta.to.shared.u64 t, %1; cvt.u32.u64 %0, t; }" : "=r"(a) : "l"(p));
    return a;
}

DINLINE void cpa16(uint32_t dst, const void* src) {
    asm volatile("cp.async.cg.shared.global [%0], [%1], 16;"
                 :: "r"(dst), "l"(__cvta_generic_to_global(src)) : "memory");
}
#define CPA_COMMIT() asm volatile("cp.async.commit_group;" ::: "memory")
#define CPA_WAIT(n)  asm volatile("cp.async.wait_group %0;" :: "n"(n) : "memory")

// m16n8k8 tf32 HMMA (target-portable, sm_80+)
DINLINE void mma8(float* d, uint32_t a0, uint32_t a1, uint32_t a2, uint32_t a3,
                  uint32_t b0, uint32_t b1) {
    asm volatile("mma.sync.aligned.m16n8k8.row.col.f32.tf32.tf32.f32 "
                 "{%0,%1,%2,%3}, {%4,%5,%6,%7}, {%8,%9}, {%0,%1,%2,%3};"
                 : "+f"(d[0]), "+f"(d[1]), "+f"(d[2]), "+f"(d[3])
                 : "r"(a0), "r"(a1), "r"(a2), "r"(a3), "r"(b0), "r"(b1));
}

// round-to-nearest tf32 (zero-mean quantization error)
DINLINE float tf32rn(float f) {
    uint32_t o;
    asm("cvt.rna.tf32.f32 %0, %1;" : "=r"(o) : "f"(f));
    return __uint_as_float(o);
}
DINLINE uint32_t fbits(float f) { return __float_as_uint(f); }

// ============================ constants ============================
static constexpr int NN = 8192;
static constexpr int DD = 256;

// GEMM tile config: BM=128, BN=256, BK=32, 3 cp.async stages
static constexpr int STAGE_FLOATS = (128 + 256) * 32;        // A 4096 + B 8192 floats
static constexpr int SMEM1_BYTES  = 3 * STAGE_FLOATS * 4;    // 147456
static constexpr int SMEM2_BYTES  = STAGE_FLOATS * 4;        // 49152

// scratch (allocation-free contract: __device__ globals)
__device__ float d_dis[NN];                 // (1 + rowsum(adj))^{-1/2}
__device__ float d_xT[(long)DD * NN];       // xT[c][n] = tf32rn(dis[n] * x[n][c])
__device__ float d_part[2L * NN * DD];      // split-K partials of adj @ X'
__device__ float d_Wr[DD * DD];             // tf32rn(W)

// ============================ K0: row sums ============================
__global__ void rowsum_kernel(const float* __restrict__ adj) {
    __shared__ float red[256];
    long i = blockIdx.x;
    const float4* row = (const float4*)(adj + i * (long)NN);
    float s = 0.f;
#pragma unroll
    for (int u = 0; u < 8; u++) {
        float4 v = row[threadIdx.x + u * 256];
        s += (v.x + v.y) + (v.z + v.w);
    }
    red[threadIdx.x] = s;
    __syncthreads();
    for (int o = 128; o > 0; o >>= 1) {
        if (threadIdx.x < o) red[threadIdx.x] += red[threadIdx.x + o];
        __syncthreads();
    }
    if (threadIdx.x == 0) d_dis[i] = rsqrtf(1.0f + red[0]);
}

// ============================ K0b: W -> tf32rn copy ============================
__global__ void wcopy_kernel(const float* __restrict__ W) {
    int idx = (blockIdx.x * 256 + threadIdx.x) * 4;
    float4 v = *(const float4*)(W + idx);
    v.x = tf32rn(v.x); v.y = tf32rn(v.y); v.z = tf32rn(v.z); v.w = tf32rn(v.w);
    *(float4*)(d_Wr + idx) = v;
}

// ============================ K1: xT[c][n] = rn(dis[n]*x[n][c]) ============================
__global__ void txpose_kernel(const float* __restrict__ x) {
    __shared__ float t[32][33];
    int n0 = blockIdx.x * 32, c0 = blockIdx.y * 32;
    int tx = threadIdx.x, ty = threadIdx.y;
#pragma unroll
    for (int u = 0; u < 4; u++) {
        int n = n0 + ty + u * 8;
        t[ty + u * 8][tx] = x[(long)n * DD + c0 + tx] * d_dis[n];
    }
    __syncthreads();
#pragma unroll
    for (int u = 0; u < 4; u++) {
        int c = c0 + ty + u * 8;
        d_xT[(long)c * NN + n0 + tx] = tf32rn(t[tx][ty + u * 8]);
    }
}

// ============================================================================
// GEMM core fragment math (shared by gemm1/gemm2)
//
// SMEM layout (per stage, k4-interleaved):
//   A: [8][128][4] floats  -> word(k,m) = ((k>>2)*128 + m)*4 + (k&3)
//   B: [8][256][4] floats  -> word(k,n) = ((k>>2)*256 + n)*4 + (k&3)
// Every mma fragment load becomes a linear 128B warp access (conflict-free).
// ============================================================================
DINLINE void compute_stage(const float* __restrict__ A, const float* __restrict__ B,
                           int wm, int wn, int lane, float acc[4][8][4]) {
    const int g4 = lane >> 2;   // group id 0..7
    const int c4 = lane & 3;    // 0..3
#pragma unroll
    for (int k8 = 0; k8 < 4; k8++) {
        const int k4a = k8 * 2, k4b = k8 * 2 + 1;
        uint32_t b[8][2];
#pragma unroll
        for (int g = 0; g < 8; g++) {
            int n = wn * 64 + g * 8 + g4;
            b[g][0] = fbits(B[(k4a * 256 + n) * 4 + c4]);
            b[g][1] = fbits(B[(k4b * 256 + n) * 4 + c4]);
        }
#pragma unroll
        for (int f = 0; f < 4; f++) {
            int m = wm * 64 + f * 16 + g4;
            uint32_t a0 = fbits(A[(k4a * 128 + m) * 4 + c4]);
            uint32_t a1 = fbits(A[(k4a * 128 + m + 8) * 4 + c4]);
            uint32_t a2 = fbits(A[(k4b * 128 + m) * 4 + c4]);
            uint32_t a3 = fbits(A[(k4b * 128 + m + 8) * 4 + c4]);
#pragma unroll
            for (int g = 0; g < 8; g++)
                mma8(acc[f][g], a0, a1, a2, a3, b[g][0], b[g][1]);
        }
    }
}

// ============================ K2: GEMM1 part[ks] = adj[m0:,ksK] @ X'[ksK,:] ============================
__global__ void __launch_bounds__(256, 1) gemm1_kernel(const float* __restrict__ adj) {
    extern __shared__ float smem[];
    const int tid = threadIdx.x, lane = tid & 31, wid = tid >> 5;
    const int wm = wid & 1, wn = wid >> 1;
    const int ks = blockIdx.x & 1;
    const long m0 = (long)(blockIdx.x >> 1) * 128;
    const long kb = (long)ks * 4096;
    const int NK = 128;                       // 4096 / 32

    const int j = tid & 7;                    // k4 chunk 0..7
    const int r = tid >> 3;                   // 0..31

    float acc[4][8][4];
#pragma unroll
    for (int f = 0; f < 4; f++)
#pragma unroll
        for (int g = 0; g < 8; g++)
#pragma unroll
            for (int q = 0; q < 4; q++) acc[f][g][q] = 0.f;

    auto load_stage = [&](int s, long k0) {
        float* As = smem + s * STAGE_FLOATS;
        float* Bs = As + 4096;
        const uint32_t abase = smem_u32(As), bbase = smem_u32(Bs);
#pragma unroll
        for (int u = 0; u < 4; u++) {
            int row = r + u * 32;
            cpa16(abase + (uint32_t)((j * 128 + row) * 16),
                  adj + (m0 + row) * (long)NN + k0 + j * 4);
        }
#pragma unroll
        for (int u = 0; u < 8; u++) {
            int n = r + u * 32;
            cpa16(bbase + (uint32_t)((j * 256 + n) * 16),
                  d_xT + (long)n * NN + k0 + j * 4);
        }
    };

    // prologue: stages 0,1
    load_stage(0, kb);       CPA_COMMIT();
    load_stage(1, kb + 32);  CPA_COMMIT();

#pragma unroll 1
    for (int kt = 0; kt < NK; kt++) {
        CPA_WAIT(1);
        __syncthreads();
        if (kt + 2 < NK) load_stage((kt + 2) % 3, kb + (long)(kt + 2) * 32);
        CPA_COMMIT();
        const float* As = smem + (kt % 3) * STAGE_FLOATS;
        compute_stage(As, As + 4096, wm, wn, lane, acc);
    }

    // epilogue: write split-K partials
    float* pbase = d_part + (long)ks * NN * DD;
#pragma unroll
    for (int f = 0; f < 4; f++) {
        int row = wm * 64 + f * 16 + (lane >> 2);
#pragma unroll
        for (int g = 0; g < 8; g++) {
            int col = wn * 64 + g * 8 + (lane & 3) * 2;
            float2 lo = make_float2(acc[f][g][0], acc[f][g][1]);
            float2 hi = make_float2(acc[f][g][2], acc[f][g][3]);
            *(float2*)(pbase + (m0 + row) * DD + col) = lo;
            *(float2*)(pbase + (m0 + row + 8) * DD + col) = hi;
        }
    }
}

// ============================ K3: GEMM2 out = relu(diag(d) * ((part0+part1+diag(d)x) @ Wr^T)) ============================
__global__ void __launch_bounds__(256, 1) gemm2_kernel(const float* __restrict__ x,
                                                       float* __restrict__ out) {
    extern __shared__ float smem[];
    const int tid = threadIdx.x, lane = tid & 31, wid = tid >> 5;
    const int wm = wid & 1, wn = wid >> 1;
    const long m0 = (long)blockIdx.x * 128;
    const int j = tid & 7, r = tid >> 3;

    float acc[4][8][4];
#pragma unroll
    for (int f = 0; f < 4; f++)
#pragma unroll
        for (int g = 0; g < 8; g++)
#pragma unroll
            for (int q = 0; q < 4; q++) acc[f][g][q] = 0.f;

    float* As = smem;
    float* Bs = smem + 4096;
    const uint32_t bbase = smem_u32(Bs);

#pragma unroll 1
    for (int st = 0; st < 8; st++) {
        const int k0 = st * 32;
        __syncthreads();   // previous stage's compute done before overwrite
        // B chunk: W rows (features), cols k0..k0+31
#pragma unroll
        for (int u = 0; u < 8; u++) {
            int n = r + u * 32;
            cpa16(bbase + (uint32_t)((j * 256 + n) * 16), d_Wr + (long)n * DD + k0 + j * 4);
        }
        CPA_COMMIT();
        // A chunk: part0 + part1 + dis*x, RN-rounded to tf32
#pragma unroll
        for (int u = 0; u < 4; u++) {
            int row = r + u * 32;
            long i = m0 + row;
            float di = d_dis[i];
            float4 p0 = *(const float4*)(d_part + i * DD + k0 + j * 4);
            float4 p1 = *(const float4*)(d_part + (long)NN * DD + i * DD + k0 + j * 4);
            float4 xv = *(const float4*)(x + i * DD + k0 + j * 4);
            float4 v;
            v.x = tf32rn(p0.x + p1.x + di * xv.x);
            v.y = tf32rn(p0.y + p1.y + di * xv.y);
            v.z = tf32rn(p0.z + p1.z + di * xv.z);
            v.w = tf32rn(p0.w + p1.w + di * xv.w);
            *(float4*)(As + (j * 128 + row) * 4) = v;
        }
        CPA_WAIT(0);
        __syncthreads();
        compute_stage(As, Bs, wm, wn, lane, acc);
    }

    // epilogue: relu(dis * acc)
#pragma unroll
    for (int f = 0; f < 4; f++) {
        int row = wm * 64 + f * 16 + (lane >> 2);
        float d0 = d_dis[m0 + row];
        float d8 = d_dis[m0 + row + 8];
#pragma unroll
        for (int g = 0; g < 8; g++) {
            int col = wn * 64 + g * 8 + (lane & 3) * 2;
            float2 lo, hi;
            lo.x = fmaxf(d0 * acc[f][g][0], 0.f);
            lo.y = fmaxf(d0 * acc[f][g][1], 0.f);
            hi.x = fmaxf(d8 * acc[f][g][2], 0.f);
            hi.y = fmaxf(d8 * acc[f][g][3], 0.f);
            *(float2*)(out + (m0 + row) * DD + col) = lo;
            *(float2*)(out + (m0 + row + 8) * DD + col) = hi;
        }
    }
}

// ============================ host ============================
extern "C" void kernel_launch(void* const* d_in, const int* in_sizes, int n_in,
                              void* d_out, int out_size) {
    const float* x   = (const float*)d_in[0];   // [8192, 256]
    const float* adj = (const float*)d_in[1];   // [8192, 8192]
    const float* W   = (const float*)d_in[2];   // [256, 256]
    float* out = (float*)d_out;

    cudaFuncSetAttribute(gemm1_kernel, cudaFuncAttributeMaxDynamicSharedMemorySize, SMEM1_BYTES);
    cudaFuncSetAttribute(gemm2_kernel, cudaFuncAttributeMaxDynamicSharedMemorySize, SMEM2_BYTES);

    rowsum_kernel<<<NN, 256>>>(adj);
    wcopy_kernel<<<DD * DD / 1024, 256>>>(W);
    txpose_kernel<<<dim3(NN / 32, DD / 32), dim3(32, 8)>>>(x);
    gemm1_kernel<<<128, 256, SMEM1_BYTES>>>(adj);
    gemm2_kernel<<<64, 256, SMEM2_BYTES>>>(x, out);
}